// round 8
// baseline (speedup 1.0000x reference)
#include <cuda_runtime.h>
#include <cstdint>
#include <cstddef>

// Problem constants (fixed shapes)
#define SEQ_L   8192
#define DMODEL  1024
#define NBATCH  2
#define NGROUP  256
#define LCACHE  128

// Tiling
#define T_TILE  128
#define NPAIR   16                       // 16 channel pairs = 32 channels per CTA
#define ZSTR    257                      // padded row stride (float2) -> conflict-free LDS
#define KSTRF   132                      // filter row stride in floats (16B-aligned rows)
#define NTHREADS 128

#define SMEM_BYTES (NPAIR * ZSTR * (int)sizeof(float2) + 8 * KSTRF * (int)sizeof(float))

// Decayed filter, precomputed once per launch: k[g,tau] = h[g,tau]*exp(-10^(2g/255) * tau/127)
__device__ float g_k[NGROUP * LCACHE];

__global__ void build_filter(const float* __restrict__ h) {
    int g = blockIdx.x;
    int tau = threadIdx.x;
    float decay = exp10f(2.0f * (float)g * (1.0f / 255.0f));
    float t = (float)tau * (1.0f / 127.0f);
    g_k[g * LCACHE + tau] = h[g * LCACHE + tau] * expf(-decay * t);
}

// 64-bit packed fp32 helpers (f32x2: 2 FMA lanes per issue)
__device__ __forceinline__ unsigned long long ld2(const float2* p) {
    return *reinterpret_cast<const unsigned long long*>(p);
}
__device__ __forceinline__ void fma2(unsigned long long& d, unsigned long long a, unsigned long long b) {
    asm("fma.rn.f32x2 %0, %1, %2, %0;" : "+l"(d) : "l"(a), "l"(b));
}
__device__ __forceinline__ unsigned long long pack2(float v) {
    unsigned long long d;
    asm("mov.b64 %0, {%1, %1};" : "=l"(d) : "f"(v));
    return d;
}

__global__ __launch_bounds__(NTHREADS, 6) void hyena_main(
    const float* __restrict__ x1g, const float* __restrict__ x2g,
    const float* __restrict__ vg,  const float* __restrict__ biasg,
    float* __restrict__ outg)
{
    extern __shared__ float2 sm[];
    float2* z_sh = sm;                                            // [NPAIR][ZSTR]
    float*  k_sh = reinterpret_cast<float*>(z_sh + NPAIR * ZSTR); // [8][KSTRF]

    const int tid   = threadIdx.x;
    const int b     = blockIdx.z;
    const int dblk  = blockIdx.y;                 // 0..31
    const int t0    = blockIdx.x * T_TILE;        // 0..8064
    const int dbase = dblk * (2 * NPAIR);         // 32 channels per block
    const int gbase = dbase >> 2;                 // first group of this CTA

    // Effective filter length for this CTA (uniform): taps with
    // exp(-decay*tau/127) < e^-10 are dropped. decay(gbase) is the CTA minimum.
    const float decay_min = exp10f(2.0f * (float)gbase * (1.0f / 255.0f));
    const int Lmax = min(128, (int)(1270.0f / decay_min) + 1);

    // ---- stage filter: 8 groups x 128 taps (scalar, 16B-aligned rows) ----
    for (int i = tid; i < 8 * LCACHE; i += NTHREADS) {
        int gl = i >> 7, tau = i & 127;
        k_sh[gl * KSTRF + tau] = g_k[(gbase + gl) * LCACHE + tau];
    }

    // ---- stage z = x2*v for window [t0-128, t0+128), float4 loads, high MLP ----
    {
        const int p = tid >> 3;                   // pair 0..15
        const int s = tid & 7;                    // 8 threads per pair
        const int d0 = dbase + 2 * p;
        const size_t r0 = ((size_t)b * DMODEL + d0) * SEQ_L;
        const size_t r1 = r0 + SEQ_L;
        float2* zrow = z_sh + p * ZSTR;
        #pragma unroll 4
        for (int c = 0; c < 8; ++c) {
            const int idx = c * 8 + s;            // float4 index 0..63
            const int tg  = t0 - 128 + 4 * idx;
            float4 a0, a1, v0, v1;
            if (tg >= 0) {
                a0 = *reinterpret_cast<const float4*>(x2g + r0 + tg);
                a1 = *reinterpret_cast<const float4*>(x2g + r1 + tg);
                v0 = *reinterpret_cast<const float4*>(vg  + r0 + tg);
                v1 = *reinterpret_cast<const float4*>(vg  + r1 + tg);
            } else {
                a0 = a1 = v0 = v1 = make_float4(0.f, 0.f, 0.f, 0.f);
            }
            float2* zp = zrow + 4 * idx;
            zp[0] = make_float2(a0.x * v0.x, a1.x * v1.x);
            zp[1] = make_float2(a0.y * v0.y, a1.y * v1.y);
            zp[2] = make_float2(a0.z * v0.z, a1.z * v1.z);
            zp[3] = make_float2(a0.w * v0.w, a1.w * v1.w);
        }
    }
    __syncthreads();

    // ---- compute: each thread owns 1 channel pair x 16 timesteps ----
    const int pair   = tid & 15;
    const int tslice = tid >> 4;                   // 0..7
    const int tb_loc = 128 + tslice * 16;          // local z index of first output t
    const float*  krow = k_sh + (pair >> 1) * KSTRF;
    const float2* zrow = z_sh + pair * ZSTR;
    const float2* zbase = zrow + (tb_loc - 127);   // window index i: z local = tb_loc-127+i

    unsigned long long acc[16];
    #pragma unroll
    for (int j = 0; j < 16; ++j) acc[j] = 0ull;

    // tau-ASCENDING loop: group g handles taps tau = 4g+dt (dt 0..3),
    // output j reads window index i = 127 - (4g+dt) + j. Group g spans
    // i in [124-4g, 142-4g]; window slides DOWN by 4 per group.
    // Circular slots: slot = i % 20. Refill (lower 4) AFTER compute:
    // new i = 120-4g+m overwrites slots of i+20 = 140-4g+m, which only
    // group g (already done) needed. Early-exit at Lmax drops the
    // negligible large-tau tail (uniform branch per CTA).
    unsigned long long r[20];
    #pragma unroll
    for (int i2 = 0; i2 < 19; ++i2)
        r[(124 + i2) % 20] = ld2(zbase + 124 + i2);

    #pragma unroll
    for (int g = 0; g < 32; ++g) {
        if (4 * g < Lmax) {
            const float4 kq = *reinterpret_cast<const float4*>(krow + 4 * g);
            {
                const unsigned long long kk = pack2(kq.x);   // tau = 4g
                #pragma unroll
                for (int j = 0; j < 16; ++j) fma2(acc[j], kk, r[(127 - 4 * g + j) % 20]);
            }
            {
                const unsigned long long kk = pack2(kq.y);   // tau = 4g+1
                #pragma unroll
                for (int j = 0; j < 16; ++j) fma2(acc[j], kk, r[(126 - 4 * g + j) % 20]);
            }
            {
                const unsigned long long kk = pack2(kq.z);   // tau = 4g+2
                #pragma unroll
                for (int j = 0; j < 16; ++j) fma2(acc[j], kk, r[(125 - 4 * g + j) % 20]);
            }
            {
                const unsigned long long kk = pack2(kq.w);   // tau = 4g+3
                #pragma unroll
                for (int j = 0; j < 16; ++j) fma2(acc[j], kk, r[(124 - 4 * g + j) % 20]);
            }
            if (g < 31) {
                #pragma unroll
                for (int m = 0; m < 4; ++m) {
                    const int i2 = 120 - 4 * g + m;
                    r[i2 % 20] = ld2(zbase + i2);
                }
            }
        }
    }

    // ---- epilogue: out = (y + z*bias) * x1 ----
    const int d0e = dbase + pair * 2;
    const float2 bb = *reinterpret_cast<const float2*>(biasg + d0e);
    const unsigned long long bpk = *reinterpret_cast<const unsigned long long*>(&bb);

    const float* x1r0 = x1g + ((size_t)b * DMODEL + d0e) * SEQ_L + t0 + tslice * 16;
    const float* x1r1 = x1r0 + SEQ_L;
    float4 xa[4], xb[4];
    #pragma unroll
    for (int q = 0; q < 4; ++q) {
        xa[q] = *reinterpret_cast<const float4*>(x1r0 + 4 * q);
        xb[q] = *reinterpret_cast<const float4*>(x1r1 + 4 * q);
    }

    float* op = outg + ((size_t)b * SEQ_L + (size_t)(t0 + tslice * 16)) * DMODEL + d0e;
    #pragma unroll
    for (int j = 0; j < 16; ++j) {
        const unsigned long long zt = ld2(zrow + (tb_loc + j));   // z[t]
        fma2(acc[j], zt, bpk);                          // y + z*bias
        float2 res = *reinterpret_cast<float2*>(&acc[j]);
        const float* pxa = reinterpret_cast<const float*>(&xa[j >> 2]);
        const float* pxb = reinterpret_cast<const float*>(&xb[j >> 2]);
        res.x *= pxa[j & 3];
        res.y *= pxb[j & 3];
        *reinterpret_cast<float2*>(op + (size_t)j * DMODEL) = res;
    }
}

extern "C" void kernel_launch(void* const* d_in, const int* in_sizes, int n_in,
                              void* d_out, int out_size) {
    const float* x1 = (const float*)d_in[0];
    const float* x2 = (const float*)d_in[1];
    const float* v  = (const float*)d_in[2];
    const float* h  = (const float*)d_in[3];
    const float* cb = (const float*)d_in[4];
    float* out = (float*)d_out;

    cudaFuncSetAttribute(hyena_main, cudaFuncAttributeMaxDynamicSharedMemorySize, SMEM_BYTES);

    build_filter<<<NGROUP, LCACHE>>>(h);

    dim3 grid(SEQ_L / T_TILE, DMODEL / (2 * NPAIR), NBATCH);  // (64, 32, 2)
    hyena_main<<<grid, NTHREADS, SMEM_BYTES>>>(x1, x2, v, cb, out);
}

// round 9
// speedup vs baseline: 1.1283x; 1.1283x over previous
#include <cuda_runtime.h>
#include <cstdint>
#include <cstddef>

// Problem constants (fixed shapes)
#define SEQ_L   8192
#define DMODEL  1024
#define NBATCH  2
#define NGROUP  256
#define LCACHE  128

// Tiling
#define T_TILE  128
#define NPAIR   16                       // 16 channel pairs = 32 channels per CTA
#define ZSTR    257                      // padded row stride (float2) -> conflict-free LDS
#define KSTRF   132                      // filter row stride in floats (16B-aligned rows)
#define NTHREADS 128

#define SMEM_BYTES (NPAIR * ZSTR * (int)sizeof(float2) + 8 * KSTRF * (int)sizeof(float))

// Decayed filter, precomputed once per launch: k[g,tau] = h[g,tau]*exp(-10^(2g/255) * tau/127)
__device__ float g_k[NGROUP * LCACHE];

__global__ void build_filter(const float* __restrict__ h) {
    int g = blockIdx.x;
    int tau = threadIdx.x;
    float decay = exp10f(2.0f * (float)g * (1.0f / 255.0f));
    float t = (float)tau * (1.0f / 127.0f);
    g_k[g * LCACHE + tau] = h[g * LCACHE + tau] * expf(-decay * t);
}

// 64-bit packed fp32 helpers (f32x2: 2 FMA lanes per issue)
__device__ __forceinline__ unsigned long long ld2(const float2* p) {
    return *reinterpret_cast<const unsigned long long*>(p);
}
__device__ __forceinline__ void fma2(unsigned long long& d, unsigned long long a, unsigned long long b) {
    asm("fma.rn.f32x2 %0, %1, %2, %0;" : "+l"(d) : "l"(a), "l"(b));
}
__device__ __forceinline__ unsigned long long pack2(float v) {
    unsigned long long d;
    asm("mov.b64 %0, {%1, %1};" : "=l"(d) : "f"(v));
    return d;
}

// Fully-unrolled causal conv over NG groups of 4 taps (tau ascending), plus epilogue.
// Window index i = 127 - tau + j (j = output 0..15); group g reads i in [124-4g, 142-4g].
// Circular slot = i % 20; refill AFTER compute (new i = 120-4g+m aliases i+20 which
// only the just-finished group needed). Zero branches inside.
template <int NG>
__device__ __forceinline__ void conv_tile(
    const float* __restrict__ krow, const float2* __restrict__ zrow,
    int tb_loc, unsigned long long bpk,
    const float* __restrict__ x1r0, const float* __restrict__ x1r1,
    float* __restrict__ op)
{
    const float2* zbase = zrow + (tb_loc - 127);

    unsigned long long acc[16];
    #pragma unroll
    for (int j = 0; j < 16; ++j) acc[j] = 0ull;

    unsigned long long r[20];
    #pragma unroll
    for (int i2 = 0; i2 < 19; ++i2)
        r[(124 + i2) % 20] = ld2(zbase + 124 + i2);

    #pragma unroll
    for (int g = 0; g < NG; ++g) {
        const float4 kq = *reinterpret_cast<const float4*>(krow + 4 * g);
        {
            const unsigned long long kk = pack2(kq.x);   // tau = 4g
            #pragma unroll
            for (int j = 0; j < 16; ++j) fma2(acc[j], kk, r[(127 - 4 * g + j) % 20]);
        }
        {
            const unsigned long long kk = pack2(kq.y);   // tau = 4g+1
            #pragma unroll
            for (int j = 0; j < 16; ++j) fma2(acc[j], kk, r[(126 - 4 * g + j) % 20]);
        }
        {
            const unsigned long long kk = pack2(kq.z);   // tau = 4g+2
            #pragma unroll
            for (int j = 0; j < 16; ++j) fma2(acc[j], kk, r[(125 - 4 * g + j) % 20]);
        }
        {
            const unsigned long long kk = pack2(kq.w);   // tau = 4g+3
            #pragma unroll
            for (int j = 0; j < 16; ++j) fma2(acc[j], kk, r[(124 - 4 * g + j) % 20]);
        }
        if (g < NG - 1) {                                 // compile-time
            #pragma unroll
            for (int m = 0; m < 4; ++m) {
                const int i2 = 120 - 4 * g + m;
                r[i2 % 20] = ld2(zbase + i2);
            }
        }
    }

    // epilogue: out = (y + z*bias) * x1
    float4 xa[4], xb[4];
    #pragma unroll
    for (int q = 0; q < 4; ++q) {
        xa[q] = *reinterpret_cast<const float4*>(x1r0 + 4 * q);
        xb[q] = *reinterpret_cast<const float4*>(x1r1 + 4 * q);
    }
    #pragma unroll
    for (int j = 0; j < 16; ++j) {
        const unsigned long long zt = ld2(zrow + (tb_loc + j));  // z[t]
        fma2(acc[j], zt, bpk);
        float2 res = *reinterpret_cast<float2*>(&acc[j]);
        const float* pxa = reinterpret_cast<const float*>(&xa[j >> 2]);
        const float* pxb = reinterpret_cast<const float*>(&xb[j >> 2]);
        res.x *= pxa[j & 3];
        res.y *= pxb[j & 3];
        *reinterpret_cast<float2*>(op + (size_t)j * DMODEL) = res;
    }
}

__global__ __launch_bounds__(NTHREADS, 6) void hyena_main(
    const float* __restrict__ x1g, const float* __restrict__ x2g,
    const float* __restrict__ vg,  const float* __restrict__ biasg,
    float* __restrict__ outg)
{
    extern __shared__ float2 sm[];
    float2* z_sh = sm;                                            // [NPAIR][ZSTR]
    float*  k_sh = reinterpret_cast<float*>(z_sh + NPAIR * ZSTR); // [8][KSTRF]

    const int tid   = threadIdx.x;
    const int b     = blockIdx.z;
    const int dblk  = blockIdx.y;                 // 0..31
    const int t0    = blockIdx.x * T_TILE;        // 0..8064
    const int dbase = dblk * (2 * NPAIR);         // 32 channels per block
    const int gbase = dbase >> 2;                 // first group of this CTA

    // ---- stage filter: 8 groups x 128 taps (scalar, 16B-aligned rows) ----
    for (int i = tid; i < 8 * LCACHE; i += NTHREADS) {
        int gl = i >> 7, tau = i & 127;
        k_sh[gl * KSTRF + tau] = g_k[(gbase + gl) * LCACHE + tau];
    }

    // ---- stage z = x2*v for window [t0-128, t0+128), float4 loads, high MLP ----
    {
        const int p = tid >> 3;                   // pair 0..15
        const int s = tid & 7;                    // 8 threads per pair
        const int d0 = dbase + 2 * p;
        const size_t r0 = ((size_t)b * DMODEL + d0) * SEQ_L;
        const size_t r1 = r0 + SEQ_L;
        float2* zrow = z_sh + p * ZSTR;
        #pragma unroll 4
        for (int c = 0; c < 8; ++c) {
            const int idx = c * 8 + s;            // float4 index 0..63
            const int tg  = t0 - 128 + 4 * idx;
            float4 a0, a1, v0, v1;
            if (tg >= 0) {
                a0 = *reinterpret_cast<const float4*>(x2g + r0 + tg);
                a1 = *reinterpret_cast<const float4*>(x2g + r1 + tg);
                v0 = *reinterpret_cast<const float4*>(vg  + r0 + tg);
                v1 = *reinterpret_cast<const float4*>(vg  + r1 + tg);
            } else {
                a0 = a1 = v0 = v1 = make_float4(0.f, 0.f, 0.f, 0.f);
            }
            float2* zp = zrow + 4 * idx;
            zp[0] = make_float2(a0.x * v0.x, a1.x * v1.x);
            zp[1] = make_float2(a0.y * v0.y, a1.y * v1.y);
            zp[2] = make_float2(a0.z * v0.z, a1.z * v1.z);
            zp[3] = make_float2(a0.w * v0.w, a1.w * v1.w);
        }
    }
    __syncthreads();

    // ---- compute identity ----
    const int pair   = tid & 15;
    const int tslice = tid >> 4;                   // 0..7
    const int tb_loc = 128 + tslice * 16;
    const float*  krow = k_sh + (pair >> 1) * KSTRF;
    const float2* zrow = z_sh + pair * ZSTR;

    const int d0e = dbase + pair * 2;
    const float2 bb = *reinterpret_cast<const float2*>(biasg + d0e);
    const unsigned long long bpk = *reinterpret_cast<const unsigned long long*>(&bb);
    const float* x1r0 = x1g + ((size_t)b * DMODEL + d0e) * SEQ_L + t0 + tslice * 16;
    const float* x1r1 = x1r0 + SEQ_L;
    float* op = outg + ((size_t)b * SEQ_L + (size_t)(t0 + tslice * 16)) * DMODEL + d0e;

    // Tap-count class per dblk: keep taps with exp(-decay*tau/127) >= e^-10,
    // decay(gbase)=10^(16*dblk/255); bound rounded up to a 16-tap class.
    // dblk<=17:128 | 18-20:96 | 21-22:64 | 23-25:48 | 26-30:32 | 31:16
    if (dblk <= 17) {
        conv_tile<32>(krow, zrow, tb_loc, bpk, x1r0, x1r1, op);
    } else if (dblk <= 20) {
        conv_tile<24>(krow, zrow, tb_loc, bpk, x1r0, x1r1, op);
    } else if (dblk <= 22) {
        conv_tile<16>(krow, zrow, tb_loc, bpk, x1r0, x1r1, op);
    } else if (dblk <= 25) {
        conv_tile<12>(krow, zrow, tb_loc, bpk, x1r0, x1r1, op);
    } else if (dblk <= 30) {
        conv_tile<8>(krow, zrow, tb_loc, bpk, x1r0, x1r1, op);
    } else {
        conv_tile<4>(krow, zrow, tb_loc, bpk, x1r0, x1r1, op);
    }
}

extern "C" void kernel_launch(void* const* d_in, const int* in_sizes, int n_in,
                              void* d_out, int out_size) {
    const float* x1 = (const float*)d_in[0];
    const float* x2 = (const float*)d_in[1];
    const float* v  = (const float*)d_in[2];
    const float* h  = (const float*)d_in[3];
    const float* cb = (const float*)d_in[4];
    float* out = (float*)d_out;

    cudaFuncSetAttribute(hyena_main, cudaFuncAttributeMaxDynamicSharedMemorySize, SMEM_BYTES);

    build_filter<<<NGROUP, LCACHE>>>(h);

    dim3 grid(SEQ_L / T_TILE, DMODEL / (2 * NPAIR), NBATCH);  // (64, 32, 2)
    hyena_main<<<grid, NTHREADS, SMEM_BYTES>>>(x1, x2, v, cb, out);
}

// round 10
// speedup vs baseline: 1.1690x; 1.0361x over previous
#include <cuda_runtime.h>
#include <cstdint>
#include <cstddef>

// Problem constants (fixed shapes)
#define SEQ_L   8192
#define DMODEL  1024
#define NBATCH  2
#define NGROUP  256
#define LCACHE  128

// Tiling
#define T_TILE  128
#define NPAIR   16                       // 16 channel pairs = 32 channels per CTA
#define ZSTR    257                      // padded row stride (float2) -> conflict-free LDS
#define KSTRF   132                      // filter row stride in floats (16B-aligned rows)
#define NTHREADS 128

#define SMEM_BYTES (NPAIR * ZSTR * (int)sizeof(float2) + 8 * KSTRF * (int)sizeof(float))

// Decayed filter, precomputed once per launch: k[g,tau] = h[g,tau]*exp(-10^(2g/255) * tau/127)
__device__ float g_k[NGROUP * LCACHE];

__global__ void build_filter(const float* __restrict__ h) {
    int g = blockIdx.x;
    int tau = threadIdx.x;
    float decay = exp10f(2.0f * (float)g * (1.0f / 255.0f));
    float t = (float)tau * (1.0f / 127.0f);
    g_k[g * LCACHE + tau] = h[g * LCACHE + tau] * expf(-decay * t);
}

// 64-bit packed fp32 helpers (f32x2: 2 FMA lanes per issue)
__device__ __forceinline__ unsigned long long ld2(const float2* p) {
    return *reinterpret_cast<const unsigned long long*>(p);
}
__device__ __forceinline__ void fma2(unsigned long long& d, unsigned long long a, unsigned long long b) {
    asm("fma.rn.f32x2 %0, %1, %2, %0;" : "+l"(d) : "l"(a), "l"(b));
}
__device__ __forceinline__ unsigned long long pack2(float v) {
    unsigned long long d;
    asm("mov.b64 %0, {%1, %1};" : "=l"(d) : "f"(v));
    return d;
}

__global__ __launch_bounds__(NTHREADS, 6) void hyena_main(
    const float* __restrict__ x1g, const float* __restrict__ x2g,
    const float* __restrict__ vg,  const float* __restrict__ biasg,
    float* __restrict__ outg)
{
    extern __shared__ float2 sm[];
    float2* z_sh = sm;                                            // [NPAIR][ZSTR]
    float*  k_sh = reinterpret_cast<float*>(z_sh + NPAIR * ZSTR); // [8][KSTRF]

    const int tid   = threadIdx.x;
    const int b     = blockIdx.z;
    const int dblk  = blockIdx.y;                 // 0..31
    const int t0    = blockIdx.x * T_TILE;        // 0..8064
    const int dbase = dblk * (2 * NPAIR);         // 32 channels per block
    const int gbase = dbase >> 2;                 // first group of this CTA

    // Effective tap count (uniform per CTA): keep exp(-decay*tau/127) >= e^-10.
    // Taps = 8 (head) + 20*NC (super-groups), NC in [1, 6].
    const float decay_min = exp10f(2.0f * (float)gbase * (1.0f / 255.0f));
    const int Lmax = min(128, (int)(1270.0f / decay_min) + 1);
    const int NC = min(6, max(1, (Lmax - 8 + 19) / 20));

    // ---- stage filter: 8 groups x 128 taps (scalar, 16B-aligned rows) ----
    for (int i = tid; i < 8 * LCACHE; i += NTHREADS) {
        int gl = i >> 7, tau = i & 127;
        k_sh[gl * KSTRF + tau] = g_k[(gbase + gl) * LCACHE + tau];
    }

    // ---- stage z = x2*v for window [t0-128, t0+128), float4 loads, high MLP ----
    {
        const int p = tid >> 3;                   // pair 0..15
        const int s = tid & 7;                    // 8 threads per pair
        const int d0 = dbase + 2 * p;
        const size_t r0 = ((size_t)b * DMODEL + d0) * SEQ_L;
        const size_t r1 = r0 + SEQ_L;
        float2* zrow = z_sh + p * ZSTR;
        #pragma unroll 4
        for (int c = 0; c < 8; ++c) {
            const int idx = c * 8 + s;            // float4 index 0..63
            const int tg  = t0 - 128 + 4 * idx;
            float4 a0, a1, v0, v1;
            if (tg >= 0) {
                a0 = *reinterpret_cast<const float4*>(x2g + r0 + tg);
                a1 = *reinterpret_cast<const float4*>(x2g + r1 + tg);
                v0 = *reinterpret_cast<const float4*>(vg  + r0 + tg);
                v1 = *reinterpret_cast<const float4*>(vg  + r1 + tg);
            } else {
                a0 = a1 = v0 = v1 = make_float4(0.f, 0.f, 0.f, 0.f);
            }
            float2* zp = zrow + 4 * idx;
            zp[0] = make_float2(a0.x * v0.x, a1.x * v1.x);
            zp[1] = make_float2(a0.y * v0.y, a1.y * v1.y);
            zp[2] = make_float2(a0.z * v0.z, a1.z * v1.z);
            zp[3] = make_float2(a0.w * v0.w, a1.w * v1.w);
        }
    }
    __syncthreads();

    // ---- compute: each thread owns 1 channel pair x 16 timesteps ----
    const int pair   = tid & 15;
    const int tslice = tid >> 4;                   // 0..7
    const int tb_loc = 128 + tslice * 16;
    const float*  krow = k_sh + (pair >> 1) * KSTRF;
    const float2* zrow = z_sh + pair * ZSTR;
    const float2* zbase = zrow + (tb_loc - 127);   // window index i: local = tb_loc-127+i

    unsigned long long acc[16];
    #pragma unroll
    for (int j = 0; j < 16; ++j) acc[j] = 0ull;

    // tau-ascending; output j reads window index i = 127 - tau + j, slot = i % 20.
    // Ring advances 4 per 4-tap group => slot pattern repeats every 5 groups (20 taps).
    // Refill happens BEFORE each group (i2 = 124-tau0+m); it clobbers slots last
    // used two groups earlier -> safe. Head = taus 0..7, then NC super-groups of 20.
    unsigned long long r[20];
    #pragma unroll
    for (int i2 = 0; i2 < 19; ++i2)
        r[(124 + i2) % 20] = ld2(zbase + 124 + i2);

    // head group 0: tau = 0..3 (covered by init)
    {
        const float4 kq = *reinterpret_cast<const float4*>(krow + 0);
        { const unsigned long long kk = pack2(kq.x);
          #pragma unroll
          for (int j = 0; j < 16; ++j) fma2(acc[j], kk, r[(127 + j) % 20]); }
        { const unsigned long long kk = pack2(kq.y);
          #pragma unroll
          for (int j = 0; j < 16; ++j) fma2(acc[j], kk, r[(126 + j) % 20]); }
        { const unsigned long long kk = pack2(kq.z);
          #pragma unroll
          for (int j = 0; j < 16; ++j) fma2(acc[j], kk, r[(125 + j) % 20]); }
        { const unsigned long long kk = pack2(kq.w);
          #pragma unroll
          for (int j = 0; j < 16; ++j) fma2(acc[j], kk, r[(124 + j) % 20]); }
    }
    // head group 1: tau = 4..7, refill i2 = 120..123 first
    {
        #pragma unroll
        for (int m = 0; m < 4; ++m) r[(120 + m) % 20] = ld2(zbase + 120 + m);
        const float4 kq = *reinterpret_cast<const float4*>(krow + 4);
        { const unsigned long long kk = pack2(kq.x);
          #pragma unroll
          for (int j = 0; j < 16; ++j) fma2(acc[j], kk, r[(123 + j) % 20]); }
        { const unsigned long long kk = pack2(kq.y);
          #pragma unroll
          for (int j = 0; j < 16; ++j) fma2(acc[j], kk, r[(122 + j) % 20]); }
        { const unsigned long long kk = pack2(kq.z);
          #pragma unroll
          for (int j = 0; j < 16; ++j) fma2(acc[j], kk, r[(121 + j) % 20]); }
        { const unsigned long long kk = pack2(kq.w);
          #pragma unroll
          for (int j = 0; j < 16; ++j) fma2(acc[j], kk, r[(120 + j) % 20]); }
    }

    // super-groups: iteration c covers taus 8+20c .. 27+20c.
    // zc = zbase - 20c keeps all offsets compile-time; kc = krow + 8 + 20c.
    {
        const float2* zc = zbase;
        const float*  kc = krow + 8;
        #pragma unroll 1
        for (int c = 0; c < NC; ++c) {
            #pragma unroll
            for (int u = 0; u < 5; ++u) {
                // group tau0_loc = 8 + 4u (relative to zc): refill i2_loc = 116-4u+m
                #pragma unroll
                for (int m = 0; m < 4; ++m)
                    r[(116 - 4 * u + m) % 20] = ld2(zc + (116 - 4 * u + m));
                const float4 kq = *reinterpret_cast<const float4*>(kc + 4 * u);
                { const unsigned long long kk = pack2(kq.x);   // tau = 8+20c+4u
                  #pragma unroll
                  for (int j = 0; j < 16; ++j) fma2(acc[j], kk, r[(119 - 4 * u + j) % 20]); }
                { const unsigned long long kk = pack2(kq.y);
                  #pragma unroll
                  for (int j = 0; j < 16; ++j) fma2(acc[j], kk, r[(118 - 4 * u + j) % 20]); }
                { const unsigned long long kk = pack2(kq.z);
                  #pragma unroll
                  for (int j = 0; j < 16; ++j) fma2(acc[j], kk, r[(117 - 4 * u + j) % 20]); }
                { const unsigned long long kk = pack2(kq.w);
                  #pragma unroll
                  for (int j = 0; j < 16; ++j) fma2(acc[j], kk, r[(116 - 4 * u + j) % 20]); }
            }
            zc -= 20;
            kc += 20;
        }
    }

    // ---- epilogue: out = (y + z*bias) * x1 ----
    const int d0e = dbase + pair * 2;
    const float2 bb = *reinterpret_cast<const float2*>(biasg + d0e);
    const unsigned long long bpk = *reinterpret_cast<const unsigned long long*>(&bb);

    const float* x1r0 = x1g + ((size_t)b * DMODEL + d0e) * SEQ_L + t0 + tslice * 16;
    const float* x1r1 = x1r0 + SEQ_L;
    float4 xa[4], xb[4];
    #pragma unroll
    for (int q = 0; q < 4; ++q) {
        xa[q] = *reinterpret_cast<const float4*>(x1r0 + 4 * q);
        xb[q] = *reinterpret_cast<const float4*>(x1r1 + 4 * q);
    }

    float* op = outg + ((size_t)b * SEQ_L + (size_t)(t0 + tslice * 16)) * DMODEL + d0e;
    #pragma unroll
    for (int j = 0; j < 16; ++j) {
        const unsigned long long zt = ld2(zrow + (tb_loc + j));   // z[t]
        fma2(acc[j], zt, bpk);                          // y + z*bias
        float2 res = *reinterpret_cast<float2*>(&acc[j]);
        const float* pxa = reinterpret_cast<const float*>(&xa[j >> 2]);
        const float* pxb = reinterpret_cast<const float*>(&xb[j >> 2]);
        res.x *= pxa[j & 3];
        res.y *= pxb[j & 3];
        *reinterpret_cast<float2*>(op + (size_t)j * DMODEL) = res;
    }
}

extern "C" void kernel_launch(void* const* d_in, const int* in_sizes, int n_in,
                              void* d_out, int out_size) {
    const float* x1 = (const float*)d_in[0];
    const float* x2 = (const float*)d_in[1];
    const float* v  = (const float*)d_in[2];
    const float* h  = (const float*)d_in[3];
    const float* cb = (const float*)d_in[4];
    float* out = (float*)d_out;

    cudaFuncSetAttribute(hyena_main, cudaFuncAttributeMaxDynamicSharedMemorySize, SMEM_BYTES);

    build_filter<<<NGROUP, LCACHE>>>(h);

    dim3 grid(SEQ_L / T_TILE, DMODEL / (2 * NPAIR), NBATCH);  // (64, 32, 2)
    hyena_main<<<grid, NTHREADS, SMEM_BYTES>>>(x1, x2, v, cb, out);
}